// round 4
// baseline (speedup 1.0000x reference)
#include <cuda_runtime.h>
#include <math.h>

#define NN 100000
#define NE 1600000
#define F  64
#define NC 40

// Scratch (no cudaMalloc allowed): two 25.6MB buffers.
__device__ float g_sum[NN * F];   // holds h + sum_{neighbors} h_j
__device__ float g_h[NN * F];     // holds layer output h

// ---------------------------------------------------------------------------
// 1) g_sum := x  (vectorized copy; initializes the GIN self-term)
// ---------------------------------------------------------------------------
__global__ void copy_init_kernel(const float4* __restrict__ src, int n4) {
    int i = blockIdx.x * blockDim.x + threadIdx.x;
    if (i < n4) ((float4*)g_sum)[i] = src[i];
}

// ---------------------------------------------------------------------------
// 2) scatter-add: g_sum[dst] += feat[src].  4 threads/edge, 16 floats each.
//    edge_index is int32 [2, NE] (JAX x64-disabled downcasts int64->int32).
//    FROM_H: read features from g_h instead of the x input pointer.
// ---------------------------------------------------------------------------
template <bool FROM_H>
__global__ void scatter_add_kernel(const float* __restrict__ feat,
                                   const int* __restrict__ ei) {
    int tid = blockIdx.x * blockDim.x + threadIdx.x;
    int e = tid >> 2;
    if (e >= NE) return;
    int part = tid & 3;
    int s = ei[e];
    int d = ei[NE + e];
    if ((unsigned)s >= NN || (unsigned)d >= NN) return;  // defensive
    const float* base = FROM_H ? g_h : feat;
    const float4* sp = (const float4*)(base + (size_t)s * F) + part * 4;
    float* dp = g_sum + (size_t)d * F + part * 16;
#pragma unroll
    for (int j = 0; j < 4; j++) {
        float4 v = sp[j];
        atomicAdd(dp + j * 4 + 0, v.x);
        atomicAdd(dp + j * 4 + 1, v.y);
        atomicAdd(dp + j * 4 + 2, v.z);
        atomicAdd(dp + j * 4 + 3, v.w);
    }
}

// ---------------------------------------------------------------------------
// 3) g_h := relu(g_sum @ W + b), W is [64,64] row-major (in,out).
//    If DUP, also writes the result back into g_sum (inits next layer's sum).
//    Block: 256 threads -> 64 rows; thread t -> row t/4, 16 contiguous cols.
// ---------------------------------------------------------------------------
template <bool DUP>
__global__ void __launch_bounds__(256)
gemm64_relu_kernel(const float* __restrict__ W,
                   const float* __restrict__ b,
                   int n) {
    __shared__ float inS[64][68];   // pad 68: conflict-free column reads
    __shared__ float Wsh[64 * 64];
    int t = threadIdx.x;
    int rbase = blockIdx.x * 64;

    for (int i = t; i < 1024; i += 256)
        ((float4*)Wsh)[i] = ((const float4*)W)[i];
    for (int i = t; i < 1024; i += 256) {
        int row = i >> 4, c4 = i & 15;
        int gr = rbase + row;
        float4 v = make_float4(0.f, 0.f, 0.f, 0.f);
        if (gr < n) v = ((const float4*)(g_sum + (size_t)gr * 64))[c4];
        *(float4*)&inS[row][c4 * 4] = v;
    }
    __syncthreads();

    int row = t >> 2;
    int cb = (t & 3) << 4;
    float acc[16];
#pragma unroll
    for (int j = 0; j < 16; j++) acc[j] = b[cb + j];
#pragma unroll
    for (int k = 0; k < 64; k++) {
        float a = inS[row][k];
        const float* wrow = &Wsh[k * 64 + cb];
#pragma unroll
        for (int j = 0; j < 16; j++) acc[j] = fmaf(a, wrow[j], acc[j]);
    }
    int gr = rbase + row;
    if (gr < n) {
        float* o0 = g_h + (size_t)gr * 64 + cb;
        float* o1 = g_sum + (size_t)gr * 64 + cb;
#pragma unroll
        for (int j = 0; j < 16; j++) {
            float v = fmaxf(acc[j], 0.f);
            o0[j] = v;
            if (DUP) o1[j] = v;
        }
    }
}

// ---------------------------------------------------------------------------
// 4) logits = g_h @ Wf + bf; out = log_softmax(logits).  One warp per row.
//    lane l owns class l (all lanes) and class 32+l (lanes 0..7).
// ---------------------------------------------------------------------------
__global__ void __launch_bounds__(256)
final_logsoftmax_kernel(const float* __restrict__ Wf,
                        const float* __restrict__ bf,
                        float* __restrict__ out,
                        int n) {
    __shared__ float Wfs[64 * NC];
    __shared__ float bfs[NC];
    __shared__ float hs[8][64];
    int t = threadIdx.x;
    for (int i = t; i < 64 * NC; i += 256) Wfs[i] = Wf[i];
    if (t < NC) bfs[t] = bf[t];

    int warp = t >> 5, lane = t & 31;
    int row = blockIdx.x * 8 + warp;
    if (row < n) {
        hs[warp][lane]      = g_h[(size_t)row * 64 + lane];
        hs[warp][lane + 32] = g_h[(size_t)row * 64 + lane + 32];
    }
    __syncthreads();
    if (row >= n) return;

    int c1 = 32 + lane;
    bool has1 = (c1 < NC);
    int idx1 = has1 ? c1 : 0;

    float acc0 = bfs[lane];
    float acc1 = has1 ? bfs[idx1] : 0.f;
#pragma unroll
    for (int k = 0; k < 64; k++) {
        float hk = hs[warp][k];
        acc0 = fmaf(hk, Wfs[k * NC + lane], acc0);
        acc1 = fmaf(hk, Wfs[k * NC + idx1], acc1);
    }

    float m = acc0;
    if (has1) m = fmaxf(m, acc1);
#pragma unroll
    for (int o = 16; o; o >>= 1) m = fmaxf(m, __shfl_xor_sync(0xffffffffu, m, o));
    float s = expf(acc0 - m) + (has1 ? expf(acc1 - m) : 0.f);
#pragma unroll
    for (int o = 16; o; o >>= 1) s += __shfl_xor_sync(0xffffffffu, s, o);
    float lse = m + logf(s);

    out[(size_t)row * NC + lane] = acc0 - lse;
    if (has1) out[(size_t)row * NC + c1] = acc1 - lse;
}

// ---------------------------------------------------------------------------
extern "C" void kernel_launch(void* const* d_in, const int* in_sizes, int n_in,
                              void* d_out, int out_size) {
    const float* x  = (const float*)d_in[0];
    const int*   ei = (const int*)d_in[1];
    const float* W1 = (const float*)d_in[2];
    const float* b1 = (const float*)d_in[3];
    const float* W2 = (const float*)d_in[4];
    const float* b2 = (const float*)d_in[5];
    const float* Wf = (const float*)d_in[6];
    const float* bf = (const float*)d_in[7];
    float*       out = (float*)d_out;

    const int n4 = NN * F / 4;                       // 1.6M float4
    const int copy_blocks = (n4 + 255) / 256;        // 6250
    const int scat_blocks = (NE * 4 + 255) / 256;    // 25000
    const int gemm_blocks = (NN + 63) / 64;          // 1563
    const int fin_blocks  = (NN + 7) / 8;            // 12500

    // Layer 1
    copy_init_kernel<<<copy_blocks, 256>>>((const float4*)x, n4);
    scatter_add_kernel<false><<<scat_blocks, 256>>>(x, ei);
    gemm64_relu_kernel<true><<<gemm_blocks, 256>>>(W1, b1, NN);   // g_h=h1, g_sum=h1
    // Layer 2
    scatter_add_kernel<true><<<scat_blocks, 256>>>(nullptr, ei);
    gemm64_relu_kernel<false><<<gemm_blocks, 256>>>(W2, b2, NN);  // g_h=h2
    // Classifier + log_softmax
    final_logsoftmax_kernel<<<fin_blocks, 256>>>(Wf, bf, out, NN);
}

// round 7
// speedup vs baseline: 4.8509x; 4.8509x over previous
#include <cuda_runtime.h>
#include <math.h>

#define NN 100000
#define NE 1600000
#define F  64
#define NC 40

// Scratch (no cudaMalloc allowed): two 25.6MB buffers.
__device__ float g_sum[NN * F];   // holds h + sum_{neighbors} h_j
__device__ float g_h[NN * F];     // holds layer output h

// ---------------------------------------------------------------------------
// 1) g_sum := x  (vectorized copy; initializes the GIN self-term)
// ---------------------------------------------------------------------------
__global__ void copy_init_kernel(const float4* __restrict__ src, int n4) {
    int i = blockIdx.x * blockDim.x + threadIdx.x;
    if (i < n4) ((float4*)g_sum)[i] = src[i];
}

// ---------------------------------------------------------------------------
// 2) scatter-add: g_sum[dst] += feat[src].  4 threads/edge, 16 floats each.
//    edge_index is int32 [2, NE].  Uses red.global.add.v4.f32 (sm_90+):
//    one L2 reduction op per 16 bytes instead of per 4 bytes.
// ---------------------------------------------------------------------------
template <bool FROM_H>
__global__ void scatter_add_kernel(const float* __restrict__ feat,
                                   const int* __restrict__ ei) {
    int tid = blockIdx.x * blockDim.x + threadIdx.x;
    int e = tid >> 2;
    if (e >= NE) return;
    int part = tid & 3;
    int s = ei[e];
    int d = ei[NE + e];
    if ((unsigned)s >= NN || (unsigned)d >= NN) return;  // defensive
    const float* base = FROM_H ? g_h : feat;
    const float4* sp = (const float4*)(base + (size_t)s * F) + part * 4;
    float* dp = g_sum + (size_t)d * F + part * 16;
#pragma unroll
    for (int j = 0; j < 4; j++) {
        float4 v = sp[j];
        asm volatile("red.global.add.v4.f32 [%0], {%1, %2, %3, %4};"
                     :: "l"(dp + j * 4), "f"(v.x), "f"(v.y), "f"(v.z), "f"(v.w)
                     : "memory");
    }
}

// ---------------------------------------------------------------------------
// 3) g_h := relu(g_sum @ W + b), W is [64,64] row-major (in,out).
//    If DUP, also writes the result into g_sum (inits next layer's sum).
//    256 threads -> 64 rows; thread t -> row t/4, quad q = t&3 -> 16 cols.
//    Bank-conflict-free: Wsh padded to 68 floats/row + k skewed by 6*q so the
//    four quads' 16B chunks land in disjoint bank octants (4k+8q+4j mod 32).
//    inS padded to 72 floats/row so the broadcast a-load is conflict-free
//    (8*row + k + 6q distinct mod 32 across the warp).
// ---------------------------------------------------------------------------
template <bool DUP>
__global__ void __launch_bounds__(256)
gemm64_relu_kernel(const float* __restrict__ W,
                   const float* __restrict__ b,
                   int n) {
    __shared__ float inS[64 * 72];
    __shared__ float Wsh[64 * 68];
    int t = threadIdx.x;
    int rbase = blockIdx.x * 64;

    for (int i = t; i < 4096; i += 256)
        Wsh[(i >> 6) * 68 + (i & 63)] = W[i];
    for (int i = t; i < 1024; i += 256) {
        int row = i >> 4, c4 = i & 15;
        int gr = rbase + row;
        float4 v = make_float4(0.f, 0.f, 0.f, 0.f);
        if (gr < n) v = ((const float4*)(g_sum + (size_t)gr * 64))[c4];
        *(float4*)&inS[row * 72 + c4 * 4] = v;
    }
    __syncthreads();

    int row = t >> 2;
    int q = t & 3;
    int cb = q << 4;
    float acc[16];
#pragma unroll
    for (int j = 0; j < 16; j++) acc[j] = b[cb + j];

#pragma unroll 16
    for (int kk = 0; kk < 64; kk++) {
        int k = (kk + 6 * q) & 63;                    // quad-skewed k order
        float a = inS[row * 72 + k];
        const float4* wp = (const float4*)&Wsh[k * 68 + cb];
        float4 w0 = wp[0], w1 = wp[1], w2 = wp[2], w3 = wp[3];
        acc[0]  = fmaf(a, w0.x, acc[0]);
        acc[1]  = fmaf(a, w0.y, acc[1]);
        acc[2]  = fmaf(a, w0.z, acc[2]);
        acc[3]  = fmaf(a, w0.w, acc[3]);
        acc[4]  = fmaf(a, w1.x, acc[4]);
        acc[5]  = fmaf(a, w1.y, acc[5]);
        acc[6]  = fmaf(a, w1.z, acc[6]);
        acc[7]  = fmaf(a, w1.w, acc[7]);
        acc[8]  = fmaf(a, w2.x, acc[8]);
        acc[9]  = fmaf(a, w2.y, acc[9]);
        acc[10] = fmaf(a, w2.z, acc[10]);
        acc[11] = fmaf(a, w2.w, acc[11]);
        acc[12] = fmaf(a, w3.x, acc[12]);
        acc[13] = fmaf(a, w3.y, acc[13]);
        acc[14] = fmaf(a, w3.z, acc[14]);
        acc[15] = fmaf(a, w3.w, acc[15]);
    }

    int gr = rbase + row;
    if (gr < n) {
        float4 o[4];
#pragma unroll
        for (int v4i = 0; v4i < 4; v4i++) {
            o[v4i].x = fmaxf(acc[v4i * 4 + 0], 0.f);
            o[v4i].y = fmaxf(acc[v4i * 4 + 1], 0.f);
            o[v4i].z = fmaxf(acc[v4i * 4 + 2], 0.f);
            o[v4i].w = fmaxf(acc[v4i * 4 + 3], 0.f);
        }
        float4* o0 = (float4*)(g_h + (size_t)gr * 64 + cb);
        float4* o1 = (float4*)(g_sum + (size_t)gr * 64 + cb);
#pragma unroll
        for (int v4i = 0; v4i < 4; v4i++) {
            o0[v4i] = o[v4i];
            if (DUP) o1[v4i] = o[v4i];
        }
    }
}

// ---------------------------------------------------------------------------
// 4) logits = g_h @ Wf + bf; out = log_softmax(logits).  One warp per row.
//    lane l owns class l (all lanes) and class 32+l (lanes 0..7).
// ---------------------------------------------------------------------------
__global__ void __launch_bounds__(256)
final_logsoftmax_kernel(const float* __restrict__ Wf,
                        const float* __restrict__ bf,
                        float* __restrict__ out,
                        int n) {
    __shared__ float Wfs[64 * NC];
    __shared__ float bfs[NC];
    __shared__ float hs[8][64];
    int t = threadIdx.x;
    for (int i = t; i < 64 * NC; i += 256) Wfs[i] = Wf[i];
    if (t < NC) bfs[t] = bf[t];

    int warp = t >> 5, lane = t & 31;
    int row = blockIdx.x * 8 + warp;
    if (row < n) {
        hs[warp][lane]      = g_h[(size_t)row * 64 + lane];
        hs[warp][lane + 32] = g_h[(size_t)row * 64 + lane + 32];
    }
    __syncthreads();
    if (row >= n) return;

    int c1 = 32 + lane;
    bool has1 = (c1 < NC);
    int idx1 = has1 ? c1 : 0;

    float acc0 = bfs[lane];
    float acc1 = has1 ? bfs[idx1] : 0.f;
#pragma unroll
    for (int k = 0; k < 64; k++) {
        float hk = hs[warp][k];
        acc0 = fmaf(hk, Wfs[k * NC + lane], acc0);
        acc1 = fmaf(hk, Wfs[k * NC + idx1], acc1);
    }

    float m = acc0;
    if (has1) m = fmaxf(m, acc1);
#pragma unroll
    for (int o = 16; o; o >>= 1) m = fmaxf(m, __shfl_xor_sync(0xffffffffu, m, o));
    float s = expf(acc0 - m) + (has1 ? expf(acc1 - m) : 0.f);
#pragma unroll
    for (int o = 16; o; o >>= 1) s += __shfl_xor_sync(0xffffffffu, s, o);
    float lse = m + logf(s);

    out[(size_t)row * NC + lane] = acc0 - lse;
    if (has1) out[(size_t)row * NC + c1] = acc1 - lse;
}

// ---------------------------------------------------------------------------
extern "C" void kernel_launch(void* const* d_in, const int* in_sizes, int n_in,
                              void* d_out, int out_size) {
    const float* x  = (const float*)d_in[0];
    const int*   ei = (const int*)d_in[1];
    const float* W1 = (const float*)d_in[2];
    const float* b1 = (const float*)d_in[3];
    const float* W2 = (const float*)d_in[4];
    const float* b2 = (const float*)d_in[5];
    const float* Wf = (const float*)d_in[6];
    const float* bf = (const float*)d_in[7];
    float*       out = (float*)d_out;

    const int n4 = NN * F / 4;                       // 1.6M float4
    const int copy_blocks = (n4 + 255) / 256;        // 6250
    const int scat_blocks = (NE * 4 + 255) / 256;    // 25000
    const int gemm_blocks = (NN + 63) / 64;          // 1563
    const int fin_blocks  = (NN + 7) / 8;            // 12500

    // Layer 1
    copy_init_kernel<<<copy_blocks, 256>>>((const float4*)x, n4);
    scatter_add_kernel<false><<<scat_blocks, 256>>>(x, ei);
    gemm64_relu_kernel<true><<<gemm_blocks, 256>>>(W1, b1, NN);   // g_h=h1, g_sum=h1
    // Layer 2
    scatter_add_kernel<true><<<scat_blocks, 256>>>(nullptr, ei);
    gemm64_relu_kernel<false><<<gemm_blocks, 256>>>(W2, b2, NN);  // g_h=h2
    // Classifier + log_softmax
    final_logsoftmax_kernel<<<fin_blocks, 256>>>(Wf, bf, out, NN);
}

// round 10
// speedup vs baseline: 6.3564x; 1.3103x over previous
#include <cuda_runtime.h>
#include <math.h>

#define NN 100000
#define NE 1600000
#define F  64
#define NC 40
#define SCAN_B 1024
#define NBLK ((NN + SCAN_B - 1) / SCAN_B)   // 98

// Scratch (__device__ globals; no cudaMalloc allowed)
__device__ float g_sum[NN * F];     // h + sum_{j in N(i)} h_j
__device__ float g_h[NN * F];       // layer output h
__device__ int   g_deg[NN];
__device__ int   g_rowptr[NN + 1];
__device__ int   g_cursor[NN];
__device__ int   g_csr[NE];         // src indices grouped by dst
__device__ int   g_bsum[NBLK];
__device__ int   g_boff[NBLK];

// ---------------------------------------------------------------------------
// CSR build: counting sort of edges by dst.  edge_index int32 [2, NE].
// ---------------------------------------------------------------------------
__global__ void zero_deg_kernel() {
    int i = blockIdx.x * blockDim.x + threadIdx.x;
    if (i < NN) g_deg[i] = 0;
}

__global__ void hist_kernel(const int* __restrict__ ei) {
    int e = blockIdx.x * blockDim.x + threadIdx.x;
    if (e >= NE) return;
    int d = ei[NE + e];
    if ((unsigned)d < NN) atomicAdd(&g_deg[d], 1);
}

__global__ void scan_blocks_kernel() {
    __shared__ int sm[SCAN_B];
    int i = blockIdx.x * SCAN_B + threadIdx.x;
    int v = (i < NN) ? g_deg[i] : 0;
    sm[threadIdx.x] = v;
    __syncthreads();
#pragma unroll
    for (int off = 1; off < SCAN_B; off <<= 1) {
        int t = (threadIdx.x >= off) ? sm[threadIdx.x - off] : 0;
        __syncthreads();
        sm[threadIdx.x] += t;
        __syncthreads();
    }
    if (i < NN) g_rowptr[i] = sm[threadIdx.x] - v;   // exclusive within block
    if (threadIdx.x == SCAN_B - 1) g_bsum[blockIdx.x] = sm[threadIdx.x];
}

__global__ void scan_sums_kernel() {
    __shared__ int sm[128];
    int t = threadIdx.x;
    int v = (t < NBLK) ? g_bsum[t] : 0;
    sm[t] = v;
    __syncthreads();
#pragma unroll
    for (int off = 1; off < 128; off <<= 1) {
        int u = (t >= off) ? sm[t - off] : 0;
        __syncthreads();
        sm[t] += u;
        __syncthreads();
    }
    if (t < NBLK) g_boff[t] = sm[t] - v;             // exclusive block offsets
}

__global__ void finalize_rowptr_kernel() {
    int i = blockIdx.x * blockDim.x + threadIdx.x;
    if (i < NN) {
        int r = g_rowptr[i] + g_boff[i / SCAN_B];
        g_rowptr[i] = r;
        g_cursor[i] = r;
    }
    if (i == 0) g_rowptr[NN] = NE;
}

__global__ void fill_csr_kernel(const int* __restrict__ ei) {
    int e = blockIdx.x * blockDim.x + threadIdx.x;
    if (e >= NE) return;
    int s = ei[e];
    int d = ei[NE + e];
    if ((unsigned)s >= NN || (unsigned)d >= NN) return;
    int pos = atomicAdd(&g_cursor[d], 1);
    g_csr[pos] = s;
}

// ---------------------------------------------------------------------------
// Pull aggregation: g_sum[i] = h[i] + sum_{j in N(i)} h[src_j].
// 4 threads per node, 16 floats each.  No atomics; coalesced store.
// ---------------------------------------------------------------------------
template <bool FROM_H>
__global__ void __launch_bounds__(256)
pull_agg_kernel(const float* __restrict__ feat) {
    int tid = blockIdx.x * blockDim.x + threadIdx.x;
    int node = tid >> 2;
    if (node >= NN) return;
    int part = tid & 3;
    const float* base = FROM_H ? g_h : feat;

    const float4* selfp = (const float4*)(base + (size_t)node * F) + part * 4;
    float4 a0 = selfp[0], a1 = selfp[1], a2 = selfp[2], a3 = selfp[3];

    int beg = g_rowptr[node], end = g_rowptr[node + 1];
    for (int j = beg; j < end; j++) {
        int s = g_csr[j];
        const float4* sp = (const float4*)(base + (size_t)s * F) + part * 4;
        float4 v0 = sp[0], v1 = sp[1], v2 = sp[2], v3 = sp[3];
        a0.x += v0.x; a0.y += v0.y; a0.z += v0.z; a0.w += v0.w;
        a1.x += v1.x; a1.y += v1.y; a1.z += v1.z; a1.w += v1.w;
        a2.x += v2.x; a2.y += v2.y; a2.z += v2.z; a2.w += v2.w;
        a3.x += v3.x; a3.y += v3.y; a3.z += v3.z; a3.w += v3.w;
    }
    float4* dp = (float4*)(g_sum + (size_t)node * F) + part * 4;
    dp[0] = a0; dp[1] = a1; dp[2] = a2; dp[3] = a3;
}

// ---------------------------------------------------------------------------
// g_h := relu(g_sum @ W + b).  128 threads, 128 rows/block.
// Thread t: rg = t>>2 (rows rg*4..rg*4+3), q = t&3 (cols q*16..q*16+15).
// Input tile transposed in smem (inT[k][row], pad 132) so the 4-row a-fetch
// is one LDS.128 broadcast.  Per k: 5 LDS.128 vs 64 FFMA -> FMA-bound.
// ---------------------------------------------------------------------------
__global__ void __launch_bounds__(128)
gemm64_relu_kernel(const float* __restrict__ W,
                   const float* __restrict__ b) {
    __shared__ float inT[64 * 132];   // [k][row], pad 132
    __shared__ float Wsh[64 * 68];    // [k][col], pad 68
    int t = threadIdx.x;
    int rbase = blockIdx.x * 128;

    for (int i = t; i < 4096; i += 128)
        Wsh[(i >> 6) * 68 + (i & 63)] = W[i];
    for (int i = t; i < 2048; i += 128) {
        int row = i & 127, c4 = i >> 7;
        int gr = rbase + row;
        float4 v = make_float4(0.f, 0.f, 0.f, 0.f);
        if (gr < NN) v = ((const float4*)(g_sum + (size_t)gr * 64))[c4];
        int k0 = c4 * 4;
        inT[(k0 + 0) * 132 + row] = v.x;
        inT[(k0 + 1) * 132 + row] = v.y;
        inT[(k0 + 2) * 132 + row] = v.z;
        inT[(k0 + 3) * 132 + row] = v.w;
    }
    __syncthreads();

    int rg = t >> 2;          // 0..31
    int q  = t & 3;
    int cb = q << 4;

    float acc[4][16];
#pragma unroll
    for (int j = 0; j < 16; j++) {
        float bj = b[cb + j];
#pragma unroll
        for (int r = 0; r < 4; r++) acc[r][j] = bj;
    }

#pragma unroll 8
    for (int k = 0; k < 64; k++) {
        float4 a = *(const float4*)&inT[k * 132 + rg * 4];
        const float4* wp = (const float4*)&Wsh[k * 68 + cb];
        float4 w0 = wp[0], w1 = wp[1], w2 = wp[2], w3 = wp[3];
        const float wv[16] = {w0.x, w0.y, w0.z, w0.w, w1.x, w1.y, w1.z, w1.w,
                              w2.x, w2.y, w2.z, w2.w, w3.x, w3.y, w3.z, w3.w};
        const float av[4] = {a.x, a.y, a.z, a.w};
#pragma unroll
        for (int r = 0; r < 4; r++)
#pragma unroll
            for (int j = 0; j < 16; j++)
                acc[r][j] = fmaf(av[r], wv[j], acc[r][j]);
    }

#pragma unroll
    for (int r = 0; r < 4; r++) {
        int gr = rbase + rg * 4 + r;
        if (gr < NN) {
            float4* o = (float4*)(g_h + (size_t)gr * 64 + cb);
#pragma unroll
            for (int v4i = 0; v4i < 4; v4i++) {
                float4 ov;
                ov.x = fmaxf(acc[r][v4i * 4 + 0], 0.f);
                ov.y = fmaxf(acc[r][v4i * 4 + 1], 0.f);
                ov.z = fmaxf(acc[r][v4i * 4 + 2], 0.f);
                ov.w = fmaxf(acc[r][v4i * 4 + 3], 0.f);
                o[v4i] = ov;
            }
        }
    }
}

// ---------------------------------------------------------------------------
// logits = g_h @ Wf + bf; out = log_softmax(logits).  One warp per row.
// ---------------------------------------------------------------------------
__global__ void __launch_bounds__(256)
final_logsoftmax_kernel(const float* __restrict__ Wf,
                        const float* __restrict__ bf,
                        float* __restrict__ out,
                        int n) {
    __shared__ float Wfs[64 * NC];
    __shared__ float bfs[NC];
    __shared__ float hs[8][64];
    int t = threadIdx.x;
    for (int i = t; i < 64 * NC; i += 256) Wfs[i] = Wf[i];
    if (t < NC) bfs[t] = bf[t];

    int warp = t >> 5, lane = t & 31;
    int row = blockIdx.x * 8 + warp;
    if (row < n) {
        hs[warp][lane]      = g_h[(size_t)row * 64 + lane];
        hs[warp][lane + 32] = g_h[(size_t)row * 64 + lane + 32];
    }
    __syncthreads();
    if (row >= n) return;

    int c1 = 32 + lane;
    bool has1 = (c1 < NC);
    int idx1 = has1 ? c1 : 0;

    float acc0 = bfs[lane];
    float acc1 = has1 ? bfs[idx1] : 0.f;
#pragma unroll
    for (int k = 0; k < 64; k++) {
        float hk = hs[warp][k];
        acc0 = fmaf(hk, Wfs[k * NC + lane], acc0);
        acc1 = fmaf(hk, Wfs[k * NC + idx1], acc1);
    }

    float m = acc0;
    if (has1) m = fmaxf(m, acc1);
#pragma unroll
    for (int o = 16; o; o >>= 1) m = fmaxf(m, __shfl_xor_sync(0xffffffffu, m, o));
    float s = expf(acc0 - m) + (has1 ? expf(acc1 - m) : 0.f);
#pragma unroll
    for (int o = 16; o; o >>= 1) s += __shfl_xor_sync(0xffffffffu, s, o);
    float lse = m + logf(s);

    out[(size_t)row * NC + lane] = acc0 - lse;
    if (has1) out[(size_t)row * NC + c1] = acc1 - lse;
}

// ---------------------------------------------------------------------------
extern "C" void kernel_launch(void* const* d_in, const int* in_sizes, int n_in,
                              void* d_out, int out_size) {
    const float* x  = (const float*)d_in[0];
    const int*   ei = (const int*)d_in[1];
    const float* W1 = (const float*)d_in[2];
    const float* b1 = (const float*)d_in[3];
    const float* W2 = (const float*)d_in[4];
    const float* b2 = (const float*)d_in[5];
    const float* Wf = (const float*)d_in[6];
    const float* bf = (const float*)d_in[7];
    float*       out = (float*)d_out;

    const int nn_blocks   = (NN + 255) / 256;        // 391
    const int ne_blocks   = (NE + 255) / 256;        // 6250
    const int pull_blocks = (NN * 4 + 255) / 256;    // 1563
    const int gemm_blocks = (NN + 127) / 128;        // 782
    const int fin_blocks  = (NN + 7) / 8;            // 12500

    // CSR build (once; reused by both layers)
    zero_deg_kernel<<<nn_blocks, 256>>>();
    hist_kernel<<<ne_blocks, 256>>>(ei);
    scan_blocks_kernel<<<NBLK, SCAN_B>>>();
    scan_sums_kernel<<<1, 128>>>();
    finalize_rowptr_kernel<<<nn_blocks, 256>>>();
    fill_csr_kernel<<<ne_blocks, 256>>>(ei);

    // Layer 1
    pull_agg_kernel<false><<<pull_blocks, 256>>>(x);
    gemm64_relu_kernel<<<gemm_blocks, 128>>>(W1, b1);
    // Layer 2
    pull_agg_kernel<true><<<pull_blocks, 256>>>(nullptr);
    gemm64_relu_kernel<<<gemm_blocks, 128>>>(W2, b2);
    // Classifier + log_softmax
    final_logsoftmax_kernel<<<fin_blocks, 256>>>(Wf, bf, out, NN);
}